// round 2
// baseline (speedup 1.0000x reference)
#include <cuda_runtime.h>

#define NROWS 262144
#define FEAT 64
#define DD 128
#define WARPS 8
#define RPW 8
#define ROWS_PER_BLOCK (WARPS * RPW)   // 64

// Scratch: double-buffered node state (padding row dropped entirely — it is
// never gathered and never part of the output).
__device__ float g_x0[(size_t)NROWS * DD];
__device__ float g_x1[(size_t)NROWS * DD];

__device__ __forceinline__ float lk(float x) { return x >= 0.f ? x : 0.01f * x; }

// ---------------------------------------------------------------------------
// Kernel A: normalize -> embed GEMM(64->128)+leaky -> layer GEMM(128->128)
//           double-leaky + residual -> layernorm * 0.5  -> g_x0
// ---------------------------------------------------------------------------
__global__ __launch_bounds__(256, 1)
void kernelA(const float* __restrict__ raw,
             const float* __restrict__ smean,
             const float* __restrict__ sstd,
             const float* __restrict__ W1,
             const float* __restrict__ b1,
             const float* __restrict__ W2,
             const float* __restrict__ b2)
{
    extern __shared__ float sm[];
    float* sW1 = sm;                         // 64*128
    float* sW2 = sW1 + FEAT * DD;            // 128*128
    float* sB1 = sW2 + DD * DD;              // 128
    float* sB2 = sB1 + DD;                   // 128
    float* sX  = sB2 + DD;                   // WARPS*RPW*FEAT
    float* sH  = sX + WARPS * RPW * FEAT;    // WARPS*RPW*DD

    const int tid = threadIdx.x;
    for (int i = tid; i < (FEAT * DD) / 4; i += 256)
        reinterpret_cast<float4*>(sW1)[i] = reinterpret_cast<const float4*>(W1)[i];
    for (int i = tid; i < (DD * DD) / 4; i += 256)
        reinterpret_cast<float4*>(sW2)[i] = reinterpret_cast<const float4*>(W2)[i];
    if (tid < DD) { sB1[tid] = b1[tid]; sB2[tid] = b2[tid]; }
    __syncthreads();

    const int warp = tid >> 5, lane = tid & 31;
    const int row0 = blockIdx.x * ROWS_PER_BLOCK + warp * RPW;
    float* xs = sX + warp * (RPW * FEAT);
    float* hs = sH + warp * (RPW * DD);

    // stage normalized inputs (row-major; reads in GEMM1 are warp-broadcasts)
    float2 m2 = reinterpret_cast<const float2*>(smean)[lane];
    float2 s2 = reinterpret_cast<const float2*>(sstd)[lane];
    const float inx = 1.f / (s2.x + 0.001f), iny = 1.f / (s2.y + 0.001f);
    #pragma unroll
    for (int r = 0; r < RPW; r++) {
        float2 v = reinterpret_cast<const float2*>(raw + (size_t)(row0 + r) * FEAT)[lane];
        v.x = (v.x - m2.x) * inx;
        v.y = (v.y - m2.y) * iny;
        reinterpret_cast<float2*>(xs + r * FEAT)[lane] = v;
    }
    __syncwarp();

    float acc[RPW][4];
    // ---- GEMM1: h = leaky(x @ W1 + b1) ----
    {
        float4 bb = reinterpret_cast<float4*>(sB1)[lane];
        #pragma unroll
        for (int r = 0; r < RPW; r++) {
            acc[r][0] = bb.x; acc[r][1] = bb.y; acc[r][2] = bb.z; acc[r][3] = bb.w;
        }
    }
    #pragma unroll 4
    for (int k = 0; k < FEAT; k++) {
        float4 w = reinterpret_cast<float4*>(sW1 + k * DD)[lane];
        #pragma unroll
        for (int r = 0; r < RPW; r++) {
            float xv = xs[r * FEAT + k];
            acc[r][0] += xv * w.x; acc[r][1] += xv * w.y;
            acc[r][2] += xv * w.z; acc[r][3] += xv * w.w;
        }
    }
    #pragma unroll
    for (int r = 0; r < RPW; r++) {
        float4 h = make_float4(lk(acc[r][0]), lk(acc[r][1]), lk(acc[r][2]), lk(acc[r][3]));
        reinterpret_cast<float4*>(hs + r * DD)[lane] = h;
    }
    __syncwarp();

    // ---- GEMM2: y = leaky(leaky(h @ W2 + b2)) + h ----
    {
        float4 bb = reinterpret_cast<float4*>(sB2)[lane];
        #pragma unroll
        for (int r = 0; r < RPW; r++) {
            acc[r][0] = bb.x; acc[r][1] = bb.y; acc[r][2] = bb.z; acc[r][3] = bb.w;
        }
    }
    #pragma unroll 4
    for (int k = 0; k < DD; k++) {
        float4 w = reinterpret_cast<float4*>(sW2 + k * DD)[lane];
        #pragma unroll
        for (int r = 0; r < RPW; r++) {
            float hv = hs[r * DD + k];
            acc[r][0] += hv * w.x; acc[r][1] += hv * w.y;
            acc[r][2] += hv * w.z; acc[r][3] += hv * w.w;
        }
    }

    // ---- layernorm * 0.5 ----
    const float invD = 1.0f / DD;
    #pragma unroll
    for (int r = 0; r < RPW; r++) {
        float4 h = reinterpret_cast<float4*>(hs + r * DD)[lane];
        float y0 = lk(lk(acc[r][0])) + h.x;
        float y1 = lk(lk(acc[r][1])) + h.y;
        float y2 = lk(lk(acc[r][2])) + h.z;
        float y3 = lk(lk(acc[r][3])) + h.w;
        float s = y0 + y1 + y2 + y3;
        float q = y0 * y0 + y1 * y1 + y2 * y2 + y3 * y3;
        #pragma unroll
        for (int off = 16; off > 0; off >>= 1) {
            s += __shfl_xor_sync(0xffffffffu, s, off);
            q += __shfl_xor_sync(0xffffffffu, q, off);
        }
        float mu  = s * invD;
        float var = q * invD - mu * mu;
        float sc  = rsqrtf(var + 1e-5f) * 0.5f;
        float4 o  = make_float4((y0 - mu) * sc, (y1 - mu) * sc,
                                (y2 - mu) * sc, (y3 - mu) * sc);
        reinterpret_cast<float4*>(g_x0 + (size_t)(row0 + r) * DD)[lane] = o;
    }
}

// ---------------------------------------------------------------------------
// Kernel B: one DEPTH step. gather-mean -> node GEMM + leaky -> rezero residual.
// PHASE 0: g_x0 -> g_x1.  PHASE 1: g_x1 -> d_out, fused with w/v GEMVs.
// ---------------------------------------------------------------------------
template<int PHASE>
__global__ __launch_bounds__(256, 1)
void kernelB(const int* __restrict__ idmap,
             const float* __restrict__ Wn,
             const float* __restrict__ bn,
             const float* __restrict__ rez,
             const float* __restrict__ Ww,
             const float* __restrict__ Wv,
             float* __restrict__ outx,
             float* __restrict__ outw,
             float* __restrict__ outv)
{
    extern __shared__ float sm[];
    float* sW = sm;                 // 128*128
    float* sB = sW + DD * DD;       // 128
    float* sG = sB + DD;            // WARPS*RPW*DD

    const int tid = threadIdx.x;
    for (int i = tid; i < (DD * DD) / 4; i += 256)
        reinterpret_cast<float4*>(sW)[i] = reinterpret_cast<const float4*>(Wn)[i];
    if (tid < DD) sB[tid] = bn[tid];
    __syncthreads();

    const float scale = 0.25f * rez[0];   // SCALE_STEPS * rezero
    const int warp = tid >> 5, lane = tid & 31;
    const int row0 = blockIdx.x * ROWS_PER_BLOCK + warp * RPW;
    float* gs = sG + warp * (RPW * DD);

    const float* __restrict__ xin = (PHASE == 0) ? g_x0 : g_x1;

    // gather-mean into shared (row-major; reads below are warp-broadcasts)
    #pragma unroll
    for (int r = 0; r < RPW; r++) {
        int2 pr = reinterpret_cast<const int2*>(idmap)[row0 + r];
        float4 va = reinterpret_cast<const float4*>(xin + (size_t)pr.x * DD)[lane];
        float4 vb = reinterpret_cast<const float4*>(xin + (size_t)pr.y * DD)[lane];
        float4 g  = make_float4(0.5f * (va.x + vb.x), 0.5f * (va.y + vb.y),
                                0.5f * (va.z + vb.z), 0.5f * (va.w + vb.w));
        reinterpret_cast<float4*>(gs + r * DD)[lane] = g;
    }
    __syncwarp();

    float acc[RPW][4];
    {
        float4 bb = reinterpret_cast<float4*>(sB)[lane];
        #pragma unroll
        for (int r = 0; r < RPW; r++) {
            acc[r][0] = bb.x; acc[r][1] = bb.y; acc[r][2] = bb.z; acc[r][3] = bb.w;
        }
    }
    #pragma unroll 4
    for (int k = 0; k < DD; k++) {
        float4 w = reinterpret_cast<float4*>(sW + k * DD)[lane];
        #pragma unroll
        for (int r = 0; r < RPW; r++) {
            float gv = gs[r * DD + k];
            acc[r][0] += gv * w.x; acc[r][1] += gv * w.y;
            acc[r][2] += gv * w.z; acc[r][3] += gv * w.w;
        }
    }

    float4 ww, vv;
    if (PHASE == 1) {
        ww = reinterpret_cast<const float4*>(Ww)[lane];
        vv = reinterpret_cast<const float4*>(Wv)[lane];
    }

    #pragma unroll
    for (int r = 0; r < RPW; r++) {
        const int row = row0 + r;
        float4 xi = reinterpret_cast<const float4*>(xin + (size_t)row * DD)[lane];
        float4 o;
        o.x = xi.x + lk(acc[r][0]) * scale;
        o.y = xi.y + lk(acc[r][1]) * scale;
        o.z = xi.z + lk(acc[r][2]) * scale;
        o.w = xi.w + lk(acc[r][3]) * scale;
        if (PHASE == 0) {
            reinterpret_cast<float4*>(g_x1 + (size_t)row * DD)[lane] = o;
        } else {
            reinterpret_cast<float4*>(outx + (size_t)row * DD)[lane] = o;
            float pw = o.x * ww.x + o.y * ww.y + o.z * ww.z + o.w * ww.w;
            float pv = o.x * vv.x + o.y * vv.y + o.z * vv.z + o.w * vv.w;
            #pragma unroll
            for (int off = 16; off > 0; off >>= 1) {
                pw += __shfl_xor_sync(0xffffffffu, pw, off);
                pv += __shfl_xor_sync(0xffffffffu, pv, off);
            }
            if (lane == 0) { outw[row] = pw; outv[row] = pv; }
        }
    }
}

extern "C" void kernel_launch(void* const* d_in, const int* in_sizes, int n_in,
                              void* d_out, int out_size)
{
    const float* raw   = (const float*)d_in[0];
    // d_in[1] = uids (unused)
    const int*   idmap = (const int*)  d_in[2];
    const float* smean = (const float*)d_in[3];
    const float* sstd  = (const float*)d_in[4];
    const float* W1    = (const float*)d_in[5];
    const float* b1    = (const float*)d_in[6];
    const float* W2    = (const float*)d_in[7];
    const float* b2    = (const float*)d_in[8];
    const float* Wn    = (const float*)d_in[9];
    const float* bn    = (const float*)d_in[10];
    const float* rez   = (const float*)d_in[11];
    const float* Ww    = (const float*)d_in[12];
    const float* Wv    = (const float*)d_in[13];
    float* out = (float*)d_out;

    const int smemA = (FEAT * DD + DD * DD + 2 * DD +
                       WARPS * RPW * FEAT + WARPS * RPW * DD) * 4;
    const int smemB = (DD * DD + DD + WARPS * RPW * DD) * 4;

    cudaFuncSetAttribute(kernelA,    cudaFuncAttributeMaxDynamicSharedMemorySize, smemA);
    cudaFuncSetAttribute(kernelB<0>, cudaFuncAttributeMaxDynamicSharedMemorySize, smemB);
    cudaFuncSetAttribute(kernelB<1>, cudaFuncAttributeMaxDynamicSharedMemorySize, smemB);

    dim3 grid(NROWS / ROWS_PER_BLOCK);
    kernelA<<<grid, 256, smemA>>>(raw, smean, sstd, W1, b1, W2, b2);
    kernelB<0><<<grid, 256, smemB>>>(idmap, Wn, bn, rez, Ww, Wv,
                                     nullptr, nullptr, nullptr);
    kernelB<1><<<grid, 256, smemB>>>(idmap, Wn, bn, rez, Ww, Wv,
                                     out,
                                     out + (size_t)NROWS * DD,
                                     out + (size_t)NROWS * DD + NROWS);
}

// round 3
// speedup vs baseline: 1.4679x; 1.4679x over previous
#include <cuda_runtime.h>

#define NROWS 262144
#define FEAT 64
#define DD 128
#define WARPS 8
#define RPW 8
#define ROWS_PER_BLOCK (WARPS * RPW)   // 64

// Scratch: double-buffered node state (padding row dropped entirely — it is
// never gathered and never part of the output).
__device__ float g_x0[(size_t)NROWS * DD];
__device__ float g_x1[(size_t)NROWS * DD];

__device__ __forceinline__ float lk(float x) { return x >= 0.f ? x : 0.01f * x; }

// ---------------------------------------------------------------------------
// Kernel A: normalize -> embed GEMM(64->128)+leaky -> layer GEMM(128->128)
//           double-leaky + residual -> layernorm * 0.5  -> g_x0
// Weights stay in global (L1-resident after first wave); smem = staging only.
// ---------------------------------------------------------------------------
__global__ __launch_bounds__(256, 2)
void kernelA(const float* __restrict__ raw,
             const float* __restrict__ smean,
             const float* __restrict__ sstd,
             const float* __restrict__ W1,
             const float* __restrict__ b1,
             const float* __restrict__ W2,
             const float* __restrict__ b2)
{
    extern __shared__ float sm[];
    float* sX = sm;                          // WARPS*RPW*FEAT
    float* sH = sX + WARPS * RPW * FEAT;     // WARPS*RPW*DD

    const int tid  = threadIdx.x;
    const int warp = tid >> 5, lane = tid & 31;
    const int row0 = blockIdx.x * ROWS_PER_BLOCK + warp * RPW;
    float* xs = sX + warp * (RPW * FEAT);
    float* hs = sH + warp * (RPW * DD);

    // stage normalized inputs (row-major; reads in GEMM1 are warp-broadcasts)
    float2 m2 = reinterpret_cast<const float2*>(smean)[lane];
    float2 s2 = reinterpret_cast<const float2*>(sstd)[lane];
    const float inx = 1.f / (s2.x + 0.001f), iny = 1.f / (s2.y + 0.001f);
    #pragma unroll
    for (int r = 0; r < RPW; r++) {
        float2 v = reinterpret_cast<const float2*>(raw + (size_t)(row0 + r) * FEAT)[lane];
        v.x = (v.x - m2.x) * inx;
        v.y = (v.y - m2.y) * iny;
        reinterpret_cast<float2*>(xs + r * FEAT)[lane] = v;
    }
    __syncwarp();

    float acc[RPW][4];
    // ---- GEMM1: h = leaky(x @ W1 + b1) ----
    {
        float4 bb = __ldg(&reinterpret_cast<const float4*>(b1)[lane]);
        #pragma unroll
        for (int r = 0; r < RPW; r++) {
            acc[r][0] = bb.x; acc[r][1] = bb.y; acc[r][2] = bb.z; acc[r][3] = bb.w;
        }
    }
    #pragma unroll
    for (int k4 = 0; k4 < FEAT; k4 += 4) {
        float4 xr[RPW];
        #pragma unroll
        for (int r = 0; r < RPW; r++)
            xr[r] = *reinterpret_cast<float4*>(xs + r * FEAT + k4);   // broadcast LDS.128
        #pragma unroll
        for (int kk = 0; kk < 4; kk++) {
            float4 w = __ldg(&reinterpret_cast<const float4*>(W1 + (k4 + kk) * DD)[lane]);
            #pragma unroll
            for (int r = 0; r < RPW; r++) {
                float xv = (kk == 0) ? xr[r].x : (kk == 1) ? xr[r].y
                         : (kk == 2) ? xr[r].z : xr[r].w;
                acc[r][0] += xv * w.x; acc[r][1] += xv * w.y;
                acc[r][2] += xv * w.z; acc[r][3] += xv * w.w;
            }
        }
    }
    #pragma unroll
    for (int r = 0; r < RPW; r++) {
        float4 h = make_float4(lk(acc[r][0]), lk(acc[r][1]), lk(acc[r][2]), lk(acc[r][3]));
        reinterpret_cast<float4*>(hs + r * DD)[lane] = h;
    }
    __syncwarp();

    // ---- GEMM2: y = leaky(leaky(h @ W2 + b2)) + h ----
    {
        float4 bb = __ldg(&reinterpret_cast<const float4*>(b2)[lane]);
        #pragma unroll
        for (int r = 0; r < RPW; r++) {
            acc[r][0] = bb.x; acc[r][1] = bb.y; acc[r][2] = bb.z; acc[r][3] = bb.w;
        }
    }
    #pragma unroll 8
    for (int k4 = 0; k4 < DD; k4 += 4) {
        float4 xr[RPW];
        #pragma unroll
        for (int r = 0; r < RPW; r++)
            xr[r] = *reinterpret_cast<float4*>(hs + r * DD + k4);
        #pragma unroll
        for (int kk = 0; kk < 4; kk++) {
            float4 w = __ldg(&reinterpret_cast<const float4*>(W2 + (k4 + kk) * DD)[lane]);
            #pragma unroll
            for (int r = 0; r < RPW; r++) {
                float hv = (kk == 0) ? xr[r].x : (kk == 1) ? xr[r].y
                         : (kk == 2) ? xr[r].z : xr[r].w;
                acc[r][0] += hv * w.x; acc[r][1] += hv * w.y;
                acc[r][2] += hv * w.z; acc[r][3] += hv * w.w;
            }
        }
    }

    // ---- layernorm * 0.5 ----
    const float invD = 1.0f / DD;
    #pragma unroll
    for (int r = 0; r < RPW; r++) {
        float4 h = reinterpret_cast<float4*>(hs + r * DD)[lane];
        float y0 = lk(lk(acc[r][0])) + h.x;
        float y1 = lk(lk(acc[r][1])) + h.y;
        float y2 = lk(lk(acc[r][2])) + h.z;
        float y3 = lk(lk(acc[r][3])) + h.w;
        float s = y0 + y1 + y2 + y3;
        float q = y0 * y0 + y1 * y1 + y2 * y2 + y3 * y3;
        #pragma unroll
        for (int off = 16; off > 0; off >>= 1) {
            s += __shfl_xor_sync(0xffffffffu, s, off);
            q += __shfl_xor_sync(0xffffffffu, q, off);
        }
        float mu  = s * invD;
        float var = q * invD - mu * mu;
        float sc  = rsqrtf(var + 1e-5f) * 0.5f;
        float4 o  = make_float4((y0 - mu) * sc, (y1 - mu) * sc,
                                (y2 - mu) * sc, (y3 - mu) * sc);
        reinterpret_cast<float4*>(g_x0 + (size_t)(row0 + r) * DD)[lane] = o;
    }
}

// ---------------------------------------------------------------------------
// Kernel B: one DEPTH step. gather-mean -> node GEMM + leaky -> rezero residual.
// PHASE 0: g_x0 -> g_x1.  PHASE 1: g_x1 -> d_out, fused with w/v GEMVs.
// ---------------------------------------------------------------------------
template<int PHASE>
__global__ __launch_bounds__(256, 2)
void kernelB(const int* __restrict__ idmap,
             const float* __restrict__ Wn,
             const float* __restrict__ bn,
             const float* __restrict__ rez,
             const float* __restrict__ Ww,
             const float* __restrict__ Wv,
             float* __restrict__ outx,
             float* __restrict__ outw,
             float* __restrict__ outv)
{
    extern __shared__ float sm[];
    float* sG = sm;                 // WARPS*RPW*DD

    const int tid  = threadIdx.x;
    const int warp = tid >> 5, lane = tid & 31;
    const int row0 = blockIdx.x * ROWS_PER_BLOCK + warp * RPW;
    float* gs = sG + warp * (RPW * DD);

    const float scale = 0.25f * __ldg(rez);   // SCALE_STEPS * rezero
    const float* __restrict__ xin = (PHASE == 0) ? g_x0 : g_x1;

    // gather-mean into shared (row-major; reads below are warp-broadcasts)
    #pragma unroll
    for (int r = 0; r < RPW; r++) {
        int2 pr = reinterpret_cast<const int2*>(idmap)[row0 + r];
        float4 va = reinterpret_cast<const float4*>(xin + (size_t)pr.x * DD)[lane];
        float4 vb = reinterpret_cast<const float4*>(xin + (size_t)pr.y * DD)[lane];
        float4 g  = make_float4(0.5f * (va.x + vb.x), 0.5f * (va.y + vb.y),
                                0.5f * (va.z + vb.z), 0.5f * (va.w + vb.w));
        reinterpret_cast<float4*>(gs + r * DD)[lane] = g;
    }
    __syncwarp();

    float acc[RPW][4];
    {
        float4 bb = __ldg(&reinterpret_cast<const float4*>(bn)[lane]);
        #pragma unroll
        for (int r = 0; r < RPW; r++) {
            acc[r][0] = bb.x; acc[r][1] = bb.y; acc[r][2] = bb.z; acc[r][3] = bb.w;
        }
    }
    #pragma unroll 8
    for (int k4 = 0; k4 < DD; k4 += 4) {
        float4 xr[RPW];
        #pragma unroll
        for (int r = 0; r < RPW; r++)
            xr[r] = *reinterpret_cast<float4*>(gs + r * DD + k4);
        #pragma unroll
        for (int kk = 0; kk < 4; kk++) {
            float4 w = __ldg(&reinterpret_cast<const float4*>(Wn + (k4 + kk) * DD)[lane]);
            #pragma unroll
            for (int r = 0; r < RPW; r++) {
                float gv = (kk == 0) ? xr[r].x : (kk == 1) ? xr[r].y
                         : (kk == 2) ? xr[r].z : xr[r].w;
                acc[r][0] += gv * w.x; acc[r][1] += gv * w.y;
                acc[r][2] += gv * w.z; acc[r][3] += gv * w.w;
            }
        }
    }

    float4 ww, vv;
    if (PHASE == 1) {
        ww = __ldg(&reinterpret_cast<const float4*>(Ww)[lane]);
        vv = __ldg(&reinterpret_cast<const float4*>(Wv)[lane]);
    }

    #pragma unroll
    for (int r = 0; r < RPW; r++) {
        const int row = row0 + r;
        float4 xi = reinterpret_cast<const float4*>(xin + (size_t)row * DD)[lane];
        float4 o;
        o.x = xi.x + lk(acc[r][0]) * scale;
        o.y = xi.y + lk(acc[r][1]) * scale;
        o.z = xi.z + lk(acc[r][2]) * scale;
        o.w = xi.w + lk(acc[r][3]) * scale;
        if (PHASE == 0) {
            reinterpret_cast<float4*>(g_x1 + (size_t)row * DD)[lane] = o;
        } else {
            reinterpret_cast<float4*>(outx + (size_t)row * DD)[lane] = o;
            float pw = o.x * ww.x + o.y * ww.y + o.z * ww.z + o.w * ww.w;
            float pv = o.x * vv.x + o.y * vv.y + o.z * vv.z + o.w * vv.w;
            #pragma unroll
            for (int off = 16; off > 0; off >>= 1) {
                pw += __shfl_xor_sync(0xffffffffu, pw, off);
                pv += __shfl_xor_sync(0xffffffffu, pv, off);
            }
            if (lane == 0) { outw[row] = pw; outv[row] = pv; }
        }
    }
}

extern "C" void kernel_launch(void* const* d_in, const int* in_sizes, int n_in,
                              void* d_out, int out_size)
{
    const float* raw   = (const float*)d_in[0];
    // d_in[1] = uids (unused)
    const int*   idmap = (const int*)  d_in[2];
    const float* smean = (const float*)d_in[3];
    const float* sstd  = (const float*)d_in[4];
    const float* W1    = (const float*)d_in[5];
    const float* b1    = (const float*)d_in[6];
    const float* W2    = (const float*)d_in[7];
    const float* b2    = (const float*)d_in[8];
    const float* Wn    = (const float*)d_in[9];
    const float* bn    = (const float*)d_in[10];
    const float* rez   = (const float*)d_in[11];
    const float* Ww    = (const float*)d_in[12];
    const float* Wv    = (const float*)d_in[13];
    float* out = (float*)d_out;

    const int smemA = (WARPS * RPW * FEAT + WARPS * RPW * DD) * 4;   // 48 KB
    const int smemB = (WARPS * RPW * DD) * 4;                        // 32 KB

    cudaFuncSetAttribute(kernelA,    cudaFuncAttributeMaxDynamicSharedMemorySize, smemA);
    cudaFuncSetAttribute(kernelB<0>, cudaFuncAttributeMaxDynamicSharedMemorySize, smemB);
    cudaFuncSetAttribute(kernelB<1>, cudaFuncAttributeMaxDynamicSharedMemorySize, smemB);

    dim3 grid(NROWS / ROWS_PER_BLOCK);
    kernelA<<<grid, 256, smemA>>>(raw, smean, sstd, W1, b1, W2, b2);
    kernelB<0><<<grid, 256, smemB>>>(idmap, Wn, bn, rez, Ww, Wv,
                                     nullptr, nullptr, nullptr);
    kernelB<1><<<grid, 256, smemB>>>(idmap, Wn, bn, rez, Ww, Wv,
                                     out,
                                     out + (size_t)NROWS * DD,
                                     out + (size_t)NROWS * DD + NROWS);
}

// round 4
// speedup vs baseline: 1.6566x; 1.1286x over previous
#include <cuda_runtime.h>

#define NROWS 262144
#define FEAT 64
#define DD 128
#define WARPS 8
#define RPW 8
#define ROWS_PER_BLOCK (WARPS * RPW)   // 64

typedef unsigned long long u64t;

// Scratch: double-buffered node state (padding row dropped — never gathered,
// never part of the output).
__device__ float g_x0[(size_t)NROWS * DD];
__device__ float g_x1[(size_t)NROWS * DD];

__device__ __forceinline__ float lk(float x) { return x >= 0.f ? x : 0.01f * x; }

__device__ __forceinline__ u64t pk2(float lo, float hi) {
    u64t r; asm("mov.b64 %0, {%1, %2};" : "=l"(r) : "f"(lo), "f"(hi)); return r;
}
__device__ __forceinline__ u64t dup2(float v) { return pk2(v, v); }
__device__ __forceinline__ void fma2(u64t& d, u64t a, u64t b) {
    asm("fma.rn.f32x2 %0, %1, %2, %0;" : "+l"(d) : "l"(a), "l"(b));
}
__device__ __forceinline__ float2 unpk(u64t v) {
    float2 f; asm("mov.b64 {%0, %1}, %2;" : "=f"(f.x), "=f"(f.y) : "l"(v)); return f;
}

// ---------------------------------------------------------------------------
// Kernel A: normalize -> embed GEMM(64->128)+leaky -> layer GEMM(128->128)
//           double-leaky + residual -> layernorm * 0.5  -> g_x0
// Weights read via LDG (L1-resident after first wave); smem = staging only.
// ---------------------------------------------------------------------------
__global__ __launch_bounds__(256, 2)
void kernelA(const float* __restrict__ raw,
             const float* __restrict__ smean,
             const float* __restrict__ sstd,
             const float* __restrict__ W1,
             const float* __restrict__ b1,
             const float* __restrict__ W2,
             const float* __restrict__ b2)
{
    extern __shared__ float sm[];
    float* sX = sm;                          // WARPS*RPW*FEAT
    float* sH = sX + WARPS * RPW * FEAT;     // WARPS*RPW*DD

    const int tid  = threadIdx.x;
    const int warp = tid >> 5, lane = tid & 31;
    const int row0 = blockIdx.x * ROWS_PER_BLOCK + warp * RPW;
    float* xs = sX + warp * (RPW * FEAT);
    float* hs = sH + warp * (RPW * DD);

    // stage normalized inputs (row-major; reads in GEMM1 are warp-broadcasts)
    float2 m2 = reinterpret_cast<const float2*>(smean)[lane];
    float2 s2 = reinterpret_cast<const float2*>(sstd)[lane];
    const float inx = 1.f / (s2.x + 0.001f), iny = 1.f / (s2.y + 0.001f);
    #pragma unroll
    for (int r = 0; r < RPW; r++) {
        float2 v = reinterpret_cast<const float2*>(raw + (size_t)(row0 + r) * FEAT)[lane];
        v.x = (v.x - m2.x) * inx;
        v.y = (v.y - m2.y) * iny;
        reinterpret_cast<float2*>(xs + r * FEAT)[lane] = v;
    }
    __syncwarp();

    u64t acc[RPW][2];
    // ---- GEMM1: h = leaky(x @ W1 + b1) ----
    {
        float4 bb = __ldg(&reinterpret_cast<const float4*>(b1)[lane]);
        u64t blo = pk2(bb.x, bb.y), bhi = pk2(bb.z, bb.w);
        #pragma unroll
        for (int r = 0; r < RPW; r++) { acc[r][0] = blo; acc[r][1] = bhi; }
    }
    #pragma unroll
    for (int k4 = 0; k4 < FEAT; k4 += 4) {
        float4 xr[RPW];
        #pragma unroll
        for (int r = 0; r < RPW; r++)
            xr[r] = *reinterpret_cast<float4*>(xs + r * FEAT + k4);   // broadcast LDS.128
        #pragma unroll
        for (int kk = 0; kk < 4; kk++) {
            ulonglong2 w = __ldg(&reinterpret_cast<const ulonglong2*>(W1 + (k4 + kk) * DD)[lane]);
            #pragma unroll
            for (int r = 0; r < RPW; r++) {
                float xv = (kk == 0) ? xr[r].x : (kk == 1) ? xr[r].y
                         : (kk == 2) ? xr[r].z : xr[r].w;
                u64t xd = dup2(xv);
                fma2(acc[r][0], xd, w.x);
                fma2(acc[r][1], xd, w.y);
            }
        }
    }
    #pragma unroll
    for (int r = 0; r < RPW; r++) {
        float2 a0 = unpk(acc[r][0]), a1 = unpk(acc[r][1]);
        float4 h = make_float4(lk(a0.x), lk(a0.y), lk(a1.x), lk(a1.y));
        reinterpret_cast<float4*>(hs + r * DD)[lane] = h;
    }
    __syncwarp();

    // ---- GEMM2: y = leaky(leaky(h @ W2 + b2)) + h ----
    {
        float4 bb = __ldg(&reinterpret_cast<const float4*>(b2)[lane]);
        u64t blo = pk2(bb.x, bb.y), bhi = pk2(bb.z, bb.w);
        #pragma unroll
        for (int r = 0; r < RPW; r++) { acc[r][0] = blo; acc[r][1] = bhi; }
    }
    #pragma unroll 8
    for (int k4 = 0; k4 < DD; k4 += 4) {
        float4 xr[RPW];
        #pragma unroll
        for (int r = 0; r < RPW; r++)
            xr[r] = *reinterpret_cast<float4*>(hs + r * DD + k4);
        #pragma unroll
        for (int kk = 0; kk < 4; kk++) {
            ulonglong2 w = __ldg(&reinterpret_cast<const ulonglong2*>(W2 + (k4 + kk) * DD)[lane]);
            #pragma unroll
            for (int r = 0; r < RPW; r++) {
                float hv = (kk == 0) ? xr[r].x : (kk == 1) ? xr[r].y
                         : (kk == 2) ? xr[r].z : xr[r].w;
                u64t hd = dup2(hv);
                fma2(acc[r][0], hd, w.x);
                fma2(acc[r][1], hd, w.y);
            }
        }
    }

    // ---- layernorm * 0.5 ----
    const float invD = 1.0f / DD;
    #pragma unroll
    for (int r = 0; r < RPW; r++) {
        float4 h = reinterpret_cast<float4*>(hs + r * DD)[lane];
        float2 a0 = unpk(acc[r][0]), a1 = unpk(acc[r][1]);
        float y0 = lk(lk(a0.x)) + h.x;
        float y1 = lk(lk(a0.y)) + h.y;
        float y2 = lk(lk(a1.x)) + h.z;
        float y3 = lk(lk(a1.y)) + h.w;
        float s = y0 + y1 + y2 + y3;
        float q = y0 * y0 + y1 * y1 + y2 * y2 + y3 * y3;
        #pragma unroll
        for (int off = 16; off > 0; off >>= 1) {
            s += __shfl_xor_sync(0xffffffffu, s, off);
            q += __shfl_xor_sync(0xffffffffu, q, off);
        }
        float mu  = s * invD;
        float var = q * invD - mu * mu;
        float sc  = rsqrtf(var + 1e-5f) * 0.5f;
        float4 o  = make_float4((y0 - mu) * sc, (y1 - mu) * sc,
                                (y2 - mu) * sc, (y3 - mu) * sc);
        reinterpret_cast<float4*>(g_x0 + (size_t)(row0 + r) * DD)[lane] = o;
    }
}

// ---------------------------------------------------------------------------
// Kernel B: one DEPTH step. gather-mean -> node GEMM + leaky -> rezero residual.
// PHASE 0: g_x0 -> g_x1.  PHASE 1: g_x1 -> d_out, fused with w/v GEMVs.
// ---------------------------------------------------------------------------
template<int PHASE>
__global__ __launch_bounds__(256, 2)
void kernelB(const int* __restrict__ idmap,
             const float* __restrict__ Wn,
             const float* __restrict__ bn,
             const float* __restrict__ rez,
             const float* __restrict__ Ww,
             const float* __restrict__ Wv,
             float* __restrict__ outx,
             float* __restrict__ outw,
             float* __restrict__ outv)
{
    extern __shared__ float sm[];
    float* sG = sm;                 // WARPS*RPW*DD

    const int tid  = threadIdx.x;
    const int warp = tid >> 5, lane = tid & 31;
    const int row0 = blockIdx.x * ROWS_PER_BLOCK + warp * RPW;
    float* gs = sG + warp * (RPW * DD);

    const float scale = 0.25f * __ldg(rez);   // SCALE_STEPS * rezero
    const float* __restrict__ xin = (PHASE == 0) ? g_x0 : g_x1;

    // gather-mean into shared (row-major; reads below are warp-broadcasts)
    #pragma unroll
    for (int r = 0; r < RPW; r++) {
        int2 pr = reinterpret_cast<const int2*>(idmap)[row0 + r];
        float4 va = reinterpret_cast<const float4*>(xin + (size_t)pr.x * DD)[lane];
        float4 vb = reinterpret_cast<const float4*>(xin + (size_t)pr.y * DD)[lane];
        float4 g  = make_float4(0.5f * (va.x + vb.x), 0.5f * (va.y + vb.y),
                                0.5f * (va.z + vb.z), 0.5f * (va.w + vb.w));
        reinterpret_cast<float4*>(gs + r * DD)[lane] = g;
    }
    __syncwarp();

    u64t acc[RPW][2];
    {
        float4 bb = __ldg(&reinterpret_cast<const float4*>(bn)[lane]);
        u64t blo = pk2(bb.x, bb.y), bhi = pk2(bb.z, bb.w);
        #pragma unroll
        for (int r = 0; r < RPW; r++) { acc[r][0] = blo; acc[r][1] = bhi; }
    }
    #pragma unroll 8
    for (int k4 = 0; k4 < DD; k4 += 4) {
        float4 xr[RPW];
        #pragma unroll
        for (int r = 0; r < RPW; r++)
            xr[r] = *reinterpret_cast<float4*>(gs + r * DD + k4);
        #pragma unroll
        for (int kk = 0; kk < 4; kk++) {
            ulonglong2 w = __ldg(&reinterpret_cast<const ulonglong2*>(Wn + (k4 + kk) * DD)[lane]);
            #pragma unroll
            for (int r = 0; r < RPW; r++) {
                float gv = (kk == 0) ? xr[r].x : (kk == 1) ? xr[r].y
                         : (kk == 2) ? xr[r].z : xr[r].w;
                u64t gd = dup2(gv);
                fma2(acc[r][0], gd, w.x);
                fma2(acc[r][1], gd, w.y);
            }
        }
    }

    float4 ww, vv;
    if (PHASE == 1) {
        ww = __ldg(&reinterpret_cast<const float4*>(Ww)[lane]);
        vv = __ldg(&reinterpret_cast<const float4*>(Wv)[lane]);
    }

    #pragma unroll
    for (int r = 0; r < RPW; r++) {
        const int row = row0 + r;
        float4 xi = reinterpret_cast<const float4*>(xin + (size_t)row * DD)[lane];
        float2 a0 = unpk(acc[r][0]), a1 = unpk(acc[r][1]);
        float4 o;
        o.x = xi.x + lk(a0.x) * scale;
        o.y = xi.y + lk(a0.y) * scale;
        o.z = xi.z + lk(a1.x) * scale;
        o.w = xi.w + lk(a1.y) * scale;
        if (PHASE == 0) {
            reinterpret_cast<float4*>(g_x1 + (size_t)row * DD)[lane] = o;
        } else {
            reinterpret_cast<float4*>(outx + (size_t)row * DD)[lane] = o;
            float pw = o.x * ww.x + o.y * ww.y + o.z * ww.z + o.w * ww.w;
            float pv = o.x * vv.x + o.y * vv.y + o.z * vv.z + o.w * vv.w;
            #pragma unroll
            for (int off = 16; off > 0; off >>= 1) {
                pw += __shfl_xor_sync(0xffffffffu, pw, off);
                pv += __shfl_xor_sync(0xffffffffu, pv, off);
            }
            if (lane == 0) { outw[row] = pw; outv[row] = pv; }
        }
    }
}

extern "C" void kernel_launch(void* const* d_in, const int* in_sizes, int n_in,
                              void* d_out, int out_size)
{
    const float* raw   = (const float*)d_in[0];
    // d_in[1] = uids (unused)
    const int*   idmap = (const int*)  d_in[2];
    const float* smean = (const float*)d_in[3];
    const float* sstd  = (const float*)d_in[4];
    const float* W1    = (const float*)d_in[5];
    const float* b1    = (const float*)d_in[6];
    const float* W2    = (const float*)d_in[7];
    const float* b2    = (const float*)d_in[8];
    const float* Wn    = (const float*)d_in[9];
    const float* bn    = (const float*)d_in[10];
    const float* rez   = (const float*)d_in[11];
    const float* Ww    = (const float*)d_in[12];
    const float* Wv    = (const float*)d_in[13];
    float* out = (float*)d_out;

    const int smemA = (WARPS * RPW * FEAT + WARPS * RPW * DD) * 4;   // 48 KB
    const int smemB = (WARPS * RPW * DD) * 4;                        // 32 KB

    cudaFuncSetAttribute(kernelA,    cudaFuncAttributeMaxDynamicSharedMemorySize, smemA);
    cudaFuncSetAttribute(kernelB<0>, cudaFuncAttributeMaxDynamicSharedMemorySize, smemB);
    cudaFuncSetAttribute(kernelB<1>, cudaFuncAttributeMaxDynamicSharedMemorySize, smemB);

    dim3 grid(NROWS / ROWS_PER_BLOCK);
    kernelA<<<grid, 256, smemA>>>(raw, smean, sstd, W1, b1, W2, b2);
    kernelB<0><<<grid, 256, smemB>>>(idmap, Wn, bn, rez, Ww, Wv,
                                     nullptr, nullptr, nullptr);
    kernelB<1><<<grid, 256, smemB>>>(idmap, Wn, bn, rez, Ww, Wv,
                                     out,
                                     out + (size_t)NROWS * DD,
                                     out + (size_t)NROWS * DD + NROWS);
}